// round 3
// baseline (speedup 1.0000x reference)
#include <cuda_runtime.h>

#define NPTS   16384
#define TPB    256
#define QPT    4                    // queries per thread
#define QCHUNK (TPB * QPT)          // 1024 queries per block
#define NCHUNK (NPTS / QCHUNK)      // 16
#define SEGS   32
#define SEGLEN (NPTS / SEGS)        // 512 refs per segment
#define SEGP   (SEGLEN / 2)         // 256 packed ref-pairs per segment

typedef unsigned long long u64;
typedef unsigned int       u32;

// Pre-packed ref pairs: g_rp[p][j][0] = {X,Y}, g_rp[p][j][1] = {Z,W}
// where X = (x_{2j} | x_{2j+1}<<32) as f32x2, W = packed 0.5*|t|^2 pair.
// p=0: refs = target (queries = predict). p=1: refs = predict.
__device__ ulonglong2 g_rp[2][NPTS / 2][2];
__device__ u32        g_minbits[2][NPTS];

__device__ __forceinline__ u64 packf(float lo, float hi) {
    return ((u64)__float_as_uint(hi) << 32) | (u64)__float_as_uint(lo);
}
__device__ __forceinline__ float2 unpack2(u64 v) {
    float2 r;
    asm("mov.b64 {%0, %1}, %2;" : "=f"(r.x), "=f"(r.y) : "l"(v));
    return r;
}
__device__ __forceinline__ u64 fma2(u64 a, u64 b, u64 c) {
    u64 d;
    asm("fma.rn.f32x2 %0, %1, %2, %3;" : "=l"(d) : "l"(a), "l"(b), "l"(c));
    return d;
}

// Order-preserving float <-> uint flip (min over floats == min over flipped uints)
__device__ __forceinline__ u32 fflip(float f) {
    u32 u = __float_as_uint(f);
    return (u & 0x80000000u) ? ~u : (u | 0x80000000u);
}
__device__ __forceinline__ float funflip(u32 u) {
    u = (u & 0x80000000u) ? (u ^ 0x80000000u) : ~u;
    return __uint_as_float(u);
}

__global__ void chamfer_prep(const float* __restrict__ pr,
                             const float* __restrict__ tg) {
    int i = blockIdx.x * blockDim.x + threadIdx.x;
    if (i >= NPTS / 2) return;
    int a = 2 * i, b = 2 * i + 1;

    float ax = tg[3 * a], ay = tg[3 * a + 1], az = tg[3 * a + 2];
    float bx = tg[3 * b], by = tg[3 * b + 1], bz = tg[3 * b + 2];
    g_rp[0][i][0] = make_ulonglong2(packf(ax, bx), packf(ay, by));
    g_rp[0][i][1] = make_ulonglong2(packf(az, bz),
                                    packf(0.5f * (ax * ax + ay * ay + az * az),
                                          0.5f * (bx * bx + by * by + bz * bz)));

    ax = pr[3 * a]; ay = pr[3 * a + 1]; az = pr[3 * a + 2];
    bx = pr[3 * b]; by = pr[3 * b + 1]; bz = pr[3 * b + 2];
    g_rp[1][i][0] = make_ulonglong2(packf(ax, bx), packf(ay, by));
    g_rp[1][i][1] = make_ulonglong2(packf(az, bz),
                                    packf(0.5f * (ax * ax + ay * ay + az * az),
                                          0.5f * (bx * bx + by * by + bz * bz)));

    g_minbits[0][a] = 0xFFFFFFFFu; g_minbits[0][b] = 0xFFFFFFFFu;
    g_minbits[1][a] = 0xFFFFFFFFu; g_minbits[1][b] = 0xFFFFFFFFu;
}

// One block: QCHUNK queries x one SEGLEN-ref segment (packed pairs in shared).
// e = 0.5|t|^2 - q.t computed 2-wide via fma.rn.f32x2 on pre-packed operands.
__global__ void __launch_bounds__(TPB)
chamfer_pass(const float* __restrict__ pr, const float* __restrict__ tg) {
    const int pass = blockIdx.z;
    const float* __restrict__ qsrc = (pass == 0) ? pr : tg;

    // 16B-aligned pre-packed pairs: sref[j][0]={X,Y}, sref[j][1]={Z,W}
    __shared__ ulonglong2 sref[SEGP][2];

    const int segBase = blockIdx.y * SEGP;
    {
        int j = threadIdx.x;                  // SEGP == TPB
        sref[j][0] = g_rp[pass][segBase + j][0];
        sref[j][1] = g_rp[pass][segBase + j][1];
    }

    const int qb = blockIdx.x * QCHUNK + threadIdx.x;
    u64 nx[QPT], ny[QPT], nz[QPT];
#pragma unroll
    for (int k = 0; k < QPT; k++) {
        int q = qb + k * TPB;
        float x = -qsrc[3 * q], y = -qsrc[3 * q + 1], z = -qsrc[3 * q + 2];
        nx[k] = packf(x, x);
        ny[k] = packf(y, y);
        nz[k] = packf(z, z);
    }

    __syncthreads();

    const float INF = __int_as_float(0x7f800000);
    float mlo[QPT], mhi[QPT];
#pragma unroll
    for (int k = 0; k < QPT; k++) { mlo[k] = INF; mhi[k] = INF; }

#pragma unroll 4
    for (int j = 0; j < SEGP; j++) {
        const ulonglong2 xy = sref[j][0];   // LDS.128 -> aligned u64 pair
        const ulonglong2 zw = sref[j][1];
#pragma unroll
        for (int k = 0; k < QPT; k++) {
            u64 e = fma2(nx[k], xy.x, zw.y);   // nq_x*X + W
            e = fma2(ny[k], xy.y, e);
            e = fma2(nz[k], zw.x, e);
            float2 ef = unpack2(e);
            mlo[k] = fminf(mlo[k], ef.x);
            mhi[k] = fminf(mhi[k], ef.y);
        }
    }

#pragma unroll
    for (int k = 0; k < QPT; k++) {
        float m = fminf(mlo[k], mhi[k]);
        atomicMin(&g_minbits[pass][qb + k * TPB], fflip(m));
    }
}

// d_q = max(2*(min_e + 0.5|q|^2), 0); loss = (sum_p0 + sum_p1) / NPTS
// Query w's come pre-packed: pass0 queries = predict = g_rp[1]; pass1 = g_rp[0].
__global__ void __launch_bounds__(1024)
chamfer_reduce(float* __restrict__ out) {
    __shared__ float sh[1024];
    float s = 0.0f;
    for (int p = threadIdx.x; p < NPTS / 2; p += 1024) {
        float2 w0 = unpack2(g_rp[1][p][1].y);   // 0.5|q|^2 for predict pair
        float e;
        e = funflip(g_minbits[0][2 * p]);
        s += fmaxf(2.0f * (e + w0.x), 0.0f);
        e = funflip(g_minbits[0][2 * p + 1]);
        s += fmaxf(2.0f * (e + w0.y), 0.0f);

        float2 w1 = unpack2(g_rp[0][p][1].y);   // 0.5|q|^2 for target pair
        e = funflip(g_minbits[1][2 * p]);
        s += fmaxf(2.0f * (e + w1.x), 0.0f);
        e = funflip(g_minbits[1][2 * p + 1]);
        s += fmaxf(2.0f * (e + w1.y), 0.0f);
    }
    sh[threadIdx.x] = s;
    __syncthreads();
#pragma unroll
    for (int off = 512; off > 0; off >>= 1) {
        if (threadIdx.x < off) sh[threadIdx.x] += sh[threadIdx.x + off];
        __syncthreads();
    }
    if (threadIdx.x == 0)
        out[0] = sh[0] * (1.0f / (float)NPTS);
}

extern "C" void kernel_launch(void* const* d_in, const int* in_sizes, int n_in,
                              void* d_out, int out_size) {
    const float* pr = (const float*)d_in[0];   // predict [1,16384,3]
    const float* tg = (const float*)d_in[1];   // target  [1,16384,3]
    float* out = (float*)d_out;

    chamfer_prep<<<(NPTS / 2 + TPB - 1) / TPB, TPB>>>(pr, tg);

    dim3 grid(NCHUNK, SEGS, 2);
    chamfer_pass<<<grid, TPB>>>(pr, tg);

    chamfer_reduce<<<1, 1024>>>(out);
}